// round 6
// baseline (speedup 1.0000x reference)
#include <cuda_runtime.h>

#define TT 64
#define BB 256
#define DD 512

// pre-activations, t-major: g_pre[row][gate][q], row = t*BB+b
__device__ __align__(16) float g_pre[TT * BB * 24];

// ---------------------------------------------------------------------------
// K1: pre[t,b,g,q] = inputs[t,b,:] @ Wg[:512,q] + bg[q] + theta_g[q]
// (unchanged from R1/R5 — proven stable)
// ---------------------------------------------------------------------------
__global__ void __launch_bounds__(256, 1) k1_gemm(
    const float* __restrict__ X,
    const float* __restrict__ Wf, const float* __restrict__ bf,
    const float* __restrict__ Wi, const float* __restrict__ bi,
    const float* __restrict__ Wu, const float* __restrict__ bu,
    const float* __restrict__ Wo, const float* __restrict__ bo,
    const float* __restrict__ thf, const float* __restrict__ thi,
    const float* __restrict__ thu, const float* __restrict__ tho)
{
    __shared__ float Wph[256 * 24];
    __shared__ float Xsh[32 * 130];

    const int tid  = threadIdx.x;
    const int warp = tid >> 5;
    const int lane = tid & 31;
    const int gate = warp & 3;
    const int rloc = ((warp >> 2) << 6) + (lane << 1);
    const int rowbase = blockIdx.x << 7;

    const float* bg = (gate == 0) ? bf  : (gate == 1) ? bi  : (gate == 2) ? bu  : bo;
    const float* tg = (gate == 0) ? thf : (gate == 1) ? thi : (gate == 2) ? thu : tho;

    float acc0[6], acc1[6];
#pragma unroll
    for (int q = 0; q < 6; q++) {
        float bias = __ldg(bg + q) + __ldg(tg + q);
        acc0[q] = bias;
        acc1[q] = bias;
    }

    const int cc = tid & 7;
    const int rr = tid >> 3;

    for (int kh = 0; kh < 2; kh++) {
        __syncthreads();
#pragma unroll
        for (int k = 0; k < 24; k++) {
            int idx = tid + (k << 8);
            int dd  = idx / 24;
            int col = idx - dd * 24;
            int g2  = col / 6;
            int q2  = col - g2 * 6;
            const float* Ws = (g2 == 0) ? Wf : (g2 == 1) ? Wi : (g2 == 2) ? Wu : Wo;
            Wph[idx] = Ws[((kh << 8) + dd) * 6 + q2];
        }
        for (int tile = 0; tile < 8; tile++) {
            const int d0 = (kh << 8) + (tile << 5);
            __syncthreads();
#pragma unroll
            for (int p = 0; p < 4; p++) {
                int r = rr + (p << 5);
                const float4 v = *reinterpret_cast<const float4*>(
                    X + (size_t)(rowbase + r) * DD + d0 + (cc << 2));
                Xsh[((cc << 2) + 0) * 130 + r] = v.x;
                Xsh[((cc << 2) + 1) * 130 + r] = v.y;
                Xsh[((cc << 2) + 2) * 130 + r] = v.z;
                Xsh[((cc << 2) + 3) * 130 + r] = v.w;
            }
            __syncthreads();
#pragma unroll
            for (int d = 0; d < 32; d++) {
                const int dd = (tile << 5) + d;
                const float2 w01 = *reinterpret_cast<const float2*>(&Wph[dd * 24 + gate * 6 + 0]);
                const float2 w23 = *reinterpret_cast<const float2*>(&Wph[dd * 24 + gate * 6 + 2]);
                const float2 w45 = *reinterpret_cast<const float2*>(&Wph[dd * 24 + gate * 6 + 4]);
                const float2 x2  = *reinterpret_cast<const float2*>(&Xsh[d * 130 + rloc]);
                acc0[0] = fmaf(x2.x, w01.x, acc0[0]);
                acc0[1] = fmaf(x2.x, w01.y, acc0[1]);
                acc0[2] = fmaf(x2.x, w23.x, acc0[2]);
                acc0[3] = fmaf(x2.x, w23.y, acc0[3]);
                acc0[4] = fmaf(x2.x, w45.x, acc0[4]);
                acc0[5] = fmaf(x2.x, w45.y, acc0[5]);
                acc1[0] = fmaf(x2.y, w01.x, acc1[0]);
                acc1[1] = fmaf(x2.y, w01.y, acc1[1]);
                acc1[2] = fmaf(x2.y, w23.x, acc1[2]);
                acc1[3] = fmaf(x2.y, w23.y, acc1[3]);
                acc1[4] = fmaf(x2.y, w45.x, acc1[4]);
                acc1[5] = fmaf(x2.y, w45.y, acc1[5]);
            }
        }
    }

    float* dst = g_pre + (size_t)(rowbase + rloc) * 24 + gate * 6;
    *reinterpret_cast<float2*>(dst + 0)      = make_float2(acc0[0], acc0[1]);
    *reinterpret_cast<float2*>(dst + 2)      = make_float2(acc0[2], acc0[3]);
    *reinterpret_cast<float2*>(dst + 4)      = make_float2(acc0[4], acc0[5]);
    *reinterpret_cast<float2*>(dst + 24 + 0) = make_float2(acc1[0], acc1[1]);
    *reinterpret_cast<float2*>(dst + 24 + 2) = make_float2(acc1[2], acc1[3]);
    *reinterpret_cast<float2*>(dst + 24 + 4) = make_float2(acc1[4], acc1[5]);
}

// tanh via degree-9 odd Taylor, valid |u| <= 0.52 (err <= ~7e-6)
__device__ __forceinline__ float tanh_poly(float u) {
    float s = u * u;
    float p = fmaf(s, 0.021869488f, -0.053968254f);
    p = fmaf(s, p, 0.13333333f);
    p = fmaf(s, p, -0.33333333f);
    return fmaf(s * u, p, u);
}

// tanh via CF rational x*(10395+1260 s+21 s^2)/(10395+4725 s+210 s^2+s^3),
// one rcp; err ~2e-5 at |x|=1, ~1e-7 at |x|=2.1. Valid for |x| <= ~2.2.
__device__ __forceinline__ float tanh_rat(float x) {
    float s = x * x;
    float num = fmaf(s, fmaf(s, 21.0f, 1260.0f), 10395.0f);
    float den = fmaf(s, fmaf(s, s + 210.0f, 4725.0f), 10395.0f);
    float r;
    asm("rcp.approx.f32 %0, %1;" : "=f"(r) : "f"(den));
    return x * num * r;
}

// ---------------------------------------------------------------------------
// K2: LSTM scan. grid 32 x 128. Warps stage 48KB of pre into SMEM; warp 0
// scans. lane = (batch<<2)|gate, h/c replicated across the 4 gate lanes.
// MUFU/step: 6 cos + 12 rcp. Phase-structured for ILP across the 6 wires.
// ---------------------------------------------------------------------------
__global__ void __launch_bounds__(128, 1) k2_scan(
    const float* __restrict__ Wf, const float* __restrict__ Wi,
    const float* __restrict__ Wu, const float* __restrict__ Wo,
    float* __restrict__ out)
{
    __shared__ float ps[TT * 192];    // 48KB : [t][bloc(8)][gate][q]

    const int tid = threadIdx.x;
    const int b0  = blockIdx.x << 3;

    {
        const float4* src = reinterpret_cast<const float4*>(g_pre);
        float4* dst = reinterpret_cast<float4*>(ps);
#pragma unroll
        for (int k = 0; k < 24; k++) {
            int i = tid + (k << 7);
            int t = i / 48;
            int c = i - t * 48;
            dst[t * 48 + c] = src[(size_t)(t * BB + b0) * 6 + c];
        }
    }
    __syncthreads();
    if (tid >= 32) return;

    const int lane = tid;
    const int g    = lane & 3;
    const int bl   = lane >> 2;
    const int b    = b0 + bl;
    const float* Wg = (g == 0) ? Wf : (g == 1) ? Wi : (g == 2) ? Wu : Wo;

    float Wh[36];
#pragma unroll
    for (int j = 0; j < 6; j++)
#pragma unroll
        for (int q = 0; q < 6; q++)
            Wh[j * 6 + q] = __ldg(Wg + (DD + j) * 6 + q);

    float h[6], c[6];
#pragma unroll
    for (int q = 0; q < 6; q++) { h[q] = 0.0f; c[q] = 0.0f; }

    const float* pb = ps + bl * 24 + g * 6;
    const unsigned mask = 0xffffffffu;
    const int qb = lane & ~3;
    const bool isU = (g == 2);

    // prefetch step 0
    float p[6];
    {
        const float2 p0 = *reinterpret_cast<const float2*>(pb + 0);
        const float2 p1 = *reinterpret_cast<const float2*>(pb + 2);
        const float2 p2 = *reinterpret_cast<const float2*>(pb + 4);
        p[0] = p0.x; p[1] = p0.y; p[2] = p1.x; p[3] = p1.y; p[4] = p2.x; p[5] = p2.y;
    }

    for (int t = 0; t < TT; t++) {
        // prefetch next step's pre (hidden behind this step's chain)
        const int tn = (t < TT - 1) ? t + 1 : t;
        const float2 n0 = *reinterpret_cast<const float2*>(pb + tn * 192 + 0);
        const float2 n1 = *reinterpret_cast<const float2*>(pb + tn * 192 + 2);
        const float2 n2 = *reinterpret_cast<const float2*>(pb + tn * 192 + 4);

        // phase 1: a[q] = p[q] + h @ Wh (two parallel partials per q)
        float a[6];
#pragma unroll
        for (int q = 0; q < 6; q++) {
            float u0 = fmaf(h[2], Wh[2 * 6 + q], fmaf(h[1], Wh[1 * 6 + q], fmaf(h[0], Wh[0 * 6 + q], p[q])));
            float u1 = fmaf(h[3], Wh[3 * 6 + q], fmaf(h[4], Wh[4 * 6 + q], h[5] * Wh[5 * 6 + q]));
            a[q] = u0 + u1;
        }

        // phase 2: z = cos(a)
        float z[6];
#pragma unroll
        for (int q = 0; q < 6; q++) z[q] = __cosf(a[q]);

        // phase 3: entanglement products (tree)
        float z01 = z[0] * z[1];
        float z23 = z[2] * z[3];
        float z45 = z[4] * z[5];
        float w[6];
        w[1] = z01;
        w[2] = z01 * z[2];
        w[3] = z01 * z23;
        w[4] = w[3] * z[4];
        w[5] = w[3] * z45;
        w[0] = z[1] * (z23 * z45);

        // phase 4: gate value. f,i,o: sigmoid = 0.5+0.5*tanh_poly(w/2) (no MUFU)
        //                      u:     tanh_rat(w) (1 rcp)
        float v[6];
#pragma unroll
        for (int q = 0; q < 6; q++) {
            if (isU) v[q] = tanh_rat(w[q]);
            else     v[q] = fmaf(0.5f, tanh_poly(0.5f * w[q]), 0.5f);
        }

        // phase 5: batched gather (24 independent shuffles)
        float fq[6], iq[6], uq[6], oq[6];
#pragma unroll
        for (int q = 0; q < 6; q++) {
            fq[q] = __shfl_sync(mask, v[q], qb + 0);
            iq[q] = __shfl_sync(mask, v[q], qb + 1);
            uq[q] = __shfl_sync(mask, v[q], qb + 2);
            oq[q] = __shfl_sync(mask, v[q], qb + 3);
        }

        // phase 6: six independent c/h chains (|c| <= 2.08 by gate bounds)
#pragma unroll
        for (int q = 0; q < 6; q++)
            c[q] = fmaf(fq[q], c[q], iq[q] * uq[q]);
#pragma unroll
        for (int q = 0; q < 6; q++)
            h[q] = oq[q] * tanh_rat(c[q]);

        if (g == 0) {
            float* o0 = out + ((size_t)t * BB + b) * 6;
            *reinterpret_cast<float2*>(o0 + 0) = make_float2(h[0], h[1]);
            *reinterpret_cast<float2*>(o0 + 2) = make_float2(h[2], h[3]);
            *reinterpret_cast<float2*>(o0 + 4) = make_float2(h[4], h[5]);
        }

        p[0] = n0.x; p[1] = n0.y; p[2] = n1.x; p[3] = n1.y; p[4] = n2.x; p[5] = n2.y;
    }

    if (g == 0) {
        float* hx = out + (size_t)TT * BB * 6 + (size_t)b * 6;
        float* cx = hx + BB * 6;
        *reinterpret_cast<float2*>(hx + 0) = make_float2(h[0], h[1]);
        *reinterpret_cast<float2*>(hx + 2) = make_float2(h[2], h[3]);
        *reinterpret_cast<float2*>(hx + 4) = make_float2(h[4], h[5]);
        *reinterpret_cast<float2*>(cx + 0) = make_float2(c[0], c[1]);
        *reinterpret_cast<float2*>(cx + 2) = make_float2(c[2], c[3]);
        *reinterpret_cast<float2*>(cx + 4) = make_float2(c[4], c[5]);
    }
}

extern "C" void kernel_launch(void* const* d_in, const int* in_sizes, int n_in,
                              void* d_out, int out_size)
{
    const float* X   = (const float*)d_in[0];
    const float* Wf  = (const float*)d_in[1];
    const float* bf  = (const float*)d_in[2];
    const float* Wi  = (const float*)d_in[3];
    const float* bi  = (const float*)d_in[4];
    const float* Wu  = (const float*)d_in[5];
    const float* bu  = (const float*)d_in[6];
    const float* Wo  = (const float*)d_in[7];
    const float* bo  = (const float*)d_in[8];
    const float* thf = (const float*)d_in[9];
    const float* thi = (const float*)d_in[10];
    const float* thu = (const float*)d_in[11];
    const float* tho = (const float*)d_in[12];
    float* out = (float*)d_out;

    k1_gemm<<<128, 256>>>(X, Wf, bf, Wi, bi, Wu, bu, Wo, bo, thf, thi, thu, tho);
    k2_scan<<<32, 128>>>(Wf, Wi, Wu, Wo, out);
}

// round 7
// speedup vs baseline: 1.4719x; 1.4719x over previous
#include <cuda_runtime.h>

#define TT 64
#define BB 256
#define DD 512

// pre-activations, t-major: g_pre[row][gate][q], row = t*BB+b
__device__ __align__(16) float g_pre[TT * BB * 24];

// ---------------------------------------------------------------------------
// K1: pre[row][j] = X[row,:] @ W*[:, j] + bias[j],  j = gate*6+q (24 outputs)
// grid 128 x 128. ONE ROW PER THREAD, all 24 outputs -> X has no cross-thread
// reuse -> stream X from GMEM (no X staging, no tile syncs). W interleaved in
// SMEM as [dd][24] (96B rows, 16B aligned), read via 6x LDS.128 broadcast.
// Single __syncthreads after the W/bias stage.
// ---------------------------------------------------------------------------
__global__ void __launch_bounds__(128, 1) k1_gemm(
    const float* __restrict__ X,
    const float* __restrict__ Wf, const float* __restrict__ bf,
    const float* __restrict__ Wi, const float* __restrict__ bi,
    const float* __restrict__ Wu, const float* __restrict__ bu,
    const float* __restrict__ Wo, const float* __restrict__ bo,
    const float* __restrict__ thf, const float* __restrict__ thi,
    const float* __restrict__ thu, const float* __restrict__ tho)
{
    __shared__ __align__(16) float Wsh[DD * 24];   // [dd][g*6+q]  48KB
    __shared__ float Bsh[24];

    const int tid = threadIdx.x;

    // stage W: col unrolled (g,q compile-time), dd strided by 128
    for (int dd = tid; dd < DD; dd += 128) {
#pragma unroll
        for (int col = 0; col < 24; col++) {
            const int g = col / 6, q = col - 6 * (col / 6);
            const float* Ws = (g == 0) ? Wf : (g == 1) ? Wi : (g == 2) ? Wu : Wo;
            Wsh[dd * 24 + col] = Ws[dd * 6 + q];
        }
    }
    if (tid < 24) {
        const int g = tid / 6, q = tid - 6 * g;
        const float* bg = (g == 0) ? bf  : (g == 1) ? bi  : (g == 2) ? bu  : bo;
        const float* tg = (g == 0) ? thf : (g == 1) ? thi : (g == 2) ? thu : tho;
        Bsh[tid] = bg[q] + tg[q];
    }
    __syncthreads();

    const int row = (blockIdx.x << 7) + tid;

    float acc[24];
#pragma unroll
    for (int j = 0; j < 24; j++) acc[j] = Bsh[j];

    const float4* xp = reinterpret_cast<const float4*>(X + (size_t)row * DD);

#pragma unroll 4
    for (int grp = 0; grp < DD / 4; grp++) {
        const float4 xv = __ldg(xp + grp);
#pragma unroll
        for (int k = 0; k < 4; k++) {
            const int dd = grp * 4 + k;
            const float xk = (k == 0) ? xv.x : (k == 1) ? xv.y : (k == 2) ? xv.z : xv.w;
            const float4* wr = reinterpret_cast<const float4*>(Wsh + dd * 24);
            const float4 w0 = wr[0], w1 = wr[1], w2 = wr[2];
            const float4 w3 = wr[3], w4 = wr[4], w5 = wr[5];
            acc[ 0] = fmaf(xk, w0.x, acc[ 0]);
            acc[ 1] = fmaf(xk, w0.y, acc[ 1]);
            acc[ 2] = fmaf(xk, w0.z, acc[ 2]);
            acc[ 3] = fmaf(xk, w0.w, acc[ 3]);
            acc[ 4] = fmaf(xk, w1.x, acc[ 4]);
            acc[ 5] = fmaf(xk, w1.y, acc[ 5]);
            acc[ 6] = fmaf(xk, w1.z, acc[ 6]);
            acc[ 7] = fmaf(xk, w1.w, acc[ 7]);
            acc[ 8] = fmaf(xk, w2.x, acc[ 8]);
            acc[ 9] = fmaf(xk, w2.y, acc[ 9]);
            acc[10] = fmaf(xk, w2.z, acc[10]);
            acc[11] = fmaf(xk, w2.w, acc[11]);
            acc[12] = fmaf(xk, w3.x, acc[12]);
            acc[13] = fmaf(xk, w3.y, acc[13]);
            acc[14] = fmaf(xk, w3.z, acc[14]);
            acc[15] = fmaf(xk, w3.w, acc[15]);
            acc[16] = fmaf(xk, w4.x, acc[16]);
            acc[17] = fmaf(xk, w4.y, acc[17]);
            acc[18] = fmaf(xk, w4.z, acc[18]);
            acc[19] = fmaf(xk, w4.w, acc[19]);
            acc[20] = fmaf(xk, w5.x, acc[20]);
            acc[21] = fmaf(xk, w5.y, acc[21]);
            acc[22] = fmaf(xk, w5.z, acc[22]);
            acc[23] = fmaf(xk, w5.w, acc[23]);
        }
    }

    float4* dst = reinterpret_cast<float4*>(g_pre + (size_t)row * 24);
#pragma unroll
    for (int j = 0; j < 6; j++)
        dst[j] = make_float4(acc[4 * j], acc[4 * j + 1], acc[4 * j + 2], acc[4 * j + 3]);
}

// tanh via degree-9 odd Taylor, valid |u| <= 0.52 (err <= ~7e-6)
__device__ __forceinline__ float tanh_poly(float u) {
    float s = u * u;
    float p = fmaf(s, 0.021869488f, -0.053968254f);
    p = fmaf(s, p, 0.13333333f);
    p = fmaf(s, p, -0.33333333f);
    return fmaf(s * u, p, u);
}

// tanh via CF rational x*(10395+1260 s+21 s^2)/(10395+4725 s+210 s^2+s^3),
// one rcp; err <= ~2e-5 for |x| <= 2.2.
__device__ __forceinline__ float tanh_rat(float x) {
    float s = x * x;
    float num = fmaf(s, fmaf(s, 21.0f, 1260.0f), 10395.0f);
    float den = fmaf(s, fmaf(s, s + 210.0f, 4725.0f), 10395.0f);
    float r;
    asm("rcp.approx.f32 %0, %1;" : "=f"(r) : "f"(den));
    return x * num * r;
}

// ---------------------------------------------------------------------------
// K2: LSTM scan (R2/R5-proven structure). grid 32 x 128. Warps stage 48KB of
// pre into SMEM; warp 0 scans. lane = (batch<<2)|gate; h,c replicated across
// the 4 gate lanes. MUFU/step: 6 cos + 12 rcp (select-based, no divergence).
// ---------------------------------------------------------------------------
__global__ void __launch_bounds__(128, 1) k2_scan(
    const float* __restrict__ Wf, const float* __restrict__ Wi,
    const float* __restrict__ Wu, const float* __restrict__ Wo,
    float* __restrict__ out)
{
    __shared__ float ps[TT * 192];    // 48KB : [t][bloc(8)][gate][q]

    const int tid = threadIdx.x;
    const int b0  = blockIdx.x << 3;

    // stage from t-major g_pre: per t, rows b0..b0+7 are 192 floats contiguous
    {
        const float4* src = reinterpret_cast<const float4*>(g_pre);
        float4* dst = reinterpret_cast<float4*>(ps);
#pragma unroll
        for (int k = 0; k < 24; k++) {
            int i = tid + (k << 7);
            int t = i / 48;
            int c = i - t * 48;
            dst[t * 48 + c] = src[(size_t)(t * BB + b0) * 6 + c];
        }
    }
    __syncthreads();
    if (tid >= 32) return;

    const int lane = tid;
    const int g    = lane & 3;
    const int bl   = lane >> 2;
    const int b    = b0 + bl;
    const float* Wg = (g == 0) ? Wf : (g == 1) ? Wi : (g == 2) ? Wu : Wo;

    float Wh[36];
#pragma unroll
    for (int j = 0; j < 6; j++)
#pragma unroll
        for (int q = 0; q < 6; q++)
            Wh[j * 6 + q] = __ldg(Wg + (DD + j) * 6 + q);

    float h[6], c[6];
#pragma unroll
    for (int q = 0; q < 6; q++) { h[q] = 0.0f; c[q] = 0.0f; }

    const float* pb = ps + bl * 24 + g * 6;
    const unsigned mask = 0xffffffffu;
    const int qb = lane & ~3;
    const bool isU = (g == 2);

#pragma unroll 2
    for (int t = 0; t < TT; t++) {
        const float2 p0 = *reinterpret_cast<const float2*>(pb + t * 192 + 0);
        const float2 p1 = *reinterpret_cast<const float2*>(pb + t * 192 + 2);
        const float2 p2 = *reinterpret_cast<const float2*>(pb + t * 192 + 4);
        float p[6] = { p0.x, p0.y, p1.x, p1.y, p2.x, p2.y };

        // a[q] = p[q] + h @ Wh (two parallel partials)
        float a[6];
#pragma unroll
        for (int q = 0; q < 6; q++) {
            float u0 = fmaf(h[2], Wh[2 * 6 + q], fmaf(h[1], Wh[1 * 6 + q], fmaf(h[0], Wh[0 * 6 + q], p[q])));
            float u1 = fmaf(h[3], Wh[3 * 6 + q], fmaf(h[4], Wh[4 * 6 + q], h[5] * Wh[5 * 6 + q]));
            a[q] = u0 + u1;
        }

        float z[6];
#pragma unroll
        for (int q = 0; q < 6; q++) z[q] = __cosf(a[q]);

        // entanglement products (tree)
        float z01 = z[0] * z[1];
        float z23 = z[2] * z[3];
        float z45 = z[4] * z[5];
        float w[6];
        w[1] = z01;
        w[2] = z01 * z[2];
        w[3] = z01 * z23;
        w[4] = w[3] * z[4];
        w[5] = w[3] * z45;
        w[0] = z[1] * (z23 * z45);

        // v: tq = tanh(w/2) poly (no MUFU);  f,i,o: 0.5+0.5*tq
        //    u: tanh(w) = 2tq/(1+tq^2)  (1 rcp), select (no divergence)
        float v[6];
#pragma unroll
        for (int q = 0; q < 6; q++) {
            float tq  = tanh_poly(0.5f * w[q]);
            float vt  = __fdividef(tq + tq, fmaf(tq, tq, 1.0f));
            v[q] = isU ? vt : fmaf(0.5f, tq, 0.5f);
        }

        // gather the 4 gates' values per wire, update c/h (replicated)
#pragma unroll
        for (int q = 0; q < 6; q++) {
            float fq = __shfl_sync(mask, v[q], qb + 0);
            float iq = __shfl_sync(mask, v[q], qb + 1);
            float uq = __shfl_sync(mask, v[q], qb + 2);
            float oq = __shfl_sync(mask, v[q], qb + 3);
            float cn = fmaf(fq, c[q], iq * uq);
            c[q] = cn;
            h[q] = oq * tanh_rat(cn);      // |cn| <= 2.08 guaranteed
        }

        if (g == 0) {
            float* o0 = out + ((size_t)t * BB + b) * 6;
            *reinterpret_cast<float2*>(o0 + 0) = make_float2(h[0], h[1]);
            *reinterpret_cast<float2*>(o0 + 2) = make_float2(h[2], h[3]);
            *reinterpret_cast<float2*>(o0 + 4) = make_float2(h[4], h[5]);
        }
    }

    if (g == 0) {
        float* hx = out + (size_t)TT * BB * 6 + (size_t)b * 6;
        float* cx = hx + BB * 6;
        *reinterpret_cast<float2*>(hx + 0) = make_float2(h[0], h[1]);
        *reinterpret_cast<float2*>(hx + 2) = make_float2(h[2], h[3]);
        *reinterpret_cast<float2*>(hx + 4) = make_float2(h[4], h[5]);
        *reinterpret_cast<float2*>(cx + 0) = make_float2(c[0], c[1]);
        *reinterpret_cast<float2*>(cx + 2) = make_float2(c[2], c[3]);
        *reinterpret_cast<float2*>(cx + 4) = make_float2(c[4], c[5]);
    }
}

extern "C" void kernel_launch(void* const* d_in, const int* in_sizes, int n_in,
                              void* d_out, int out_size)
{
    const float* X   = (const float*)d_in[0];
    const float* Wf  = (const float*)d_in[1];
    const float* bf  = (const float*)d_in[2];
    const float* Wi  = (const float*)d_in[3];
    const float* bi  = (const float*)d_in[4];
    const float* Wu  = (const float*)d_in[5];
    const float* bu  = (const float*)d_in[6];
    const float* Wo  = (const float*)d_in[7];
    const float* bo  = (const float*)d_in[8];
    const float* thf = (const float*)d_in[9];
    const float* thi = (const float*)d_in[10];
    const float* thu = (const float*)d_in[11];
    const float* tho = (const float*)d_in[12];
    float* out = (float*)d_out;

    k1_gemm<<<128, 128>>>(X, Wf, bf, Wi, bi, Wu, bu, Wo, bo, thf, thi, thu, tho);
    k2_scan<<<32, 128>>>(Wf, Wi, Wu, Wo, out);
}